// round 1
// baseline (speedup 1.0000x reference)
#include <cuda_runtime.h>

// ---------------- problem constants ----------------
#define BSZ 512
#define WN  50
#define TN  50
#define HN  1024
#define H4  4096
#define VN  1024
#define MVN 64
#define LN  30
#define SOS 0
#define EOS 1

// ---------------- device scratch (allowed: __device__ globals) ----------------
__device__ float g_escore[VN];
__device__ float g_c0s[1];
__device__ float g_r[BSZ * HN];
__device__ float g_h[BSZ * HN];
__device__ float g_c[BSZ * HN];
__device__ float g_gates[BSZ * H4];
__device__ float g_m[BSZ];
__device__ float g_message[LN * BSZ * MVN];
__device__ float g_msgmask[LN * BSZ];
__device__ float g_genxb[H4];
__device__ float g_sethb[H4];
__device__ float g_mencbias[H4];
__device__ float g_decbias[H4];
__device__ float g_mencxb[(size_t)LN * BSZ * H4];   // 240 MB
__device__ float g_decx[(size_t)TN * BSZ * HN];     // 100 MB
__device__ float g_decxb[(size_t)TN * BSZ * H4];    // 400 MB
__device__ float g_dech[(size_t)TN * BSZ * HN];     // 100 MB

__device__ __forceinline__ float sigf(float x) { return 1.0f / (1.0f + expf(-x)); }

// ---------------- tiled SGEMM: C[M,N] = A[M,K] @ W[N,K]^T (+bias[n]) (+add[m,n]) ----------------
// Requires M%128==0, N%128==0, K%8==0. 256 threads, 128x128 tile, 8x8 per thread.
__global__ void __launch_bounds__(256) k_gemm(const float* __restrict__ A,
                                              const float* __restrict__ W,
                                              const float* __restrict__ bias,
                                              const float* __restrict__ add,
                                              float* __restrict__ C,
                                              int M, int N, int K) {
    __shared__ float As[8][128];
    __shared__ float Bs[8][128];
    const int tid = threadIdx.x;
    const int bm = blockIdx.y * 128;
    const int bn = blockIdx.x * 128;
    const int tx = tid & 15;       // n-dir
    const int ty = tid >> 4;       // m-dir
    const int lrow = tid >> 1;     // 0..127
    const int lcol = (tid & 1) * 4;

    const float* Ab = A + (size_t)(bm + lrow) * K + lcol;
    const float* Wb = W + (size_t)(bn + lrow) * K + lcol;

    float acc[8][8];
#pragma unroll
    for (int i = 0; i < 8; i++)
#pragma unroll
        for (int j = 0; j < 8; j++) acc[i][j] = 0.0f;

    for (int k0 = 0; k0 < K; k0 += 8) {
        float4 av = *(const float4*)(Ab + k0);
        float4 bv = *(const float4*)(Wb + k0);
        As[lcol + 0][lrow] = av.x; As[lcol + 1][lrow] = av.y;
        As[lcol + 2][lrow] = av.z; As[lcol + 3][lrow] = av.w;
        Bs[lcol + 0][lrow] = bv.x; Bs[lcol + 1][lrow] = bv.y;
        Bs[lcol + 2][lrow] = bv.z; Bs[lcol + 3][lrow] = bv.w;
        __syncthreads();
#pragma unroll
        for (int kk = 0; kk < 8; kk++) {
            float a[8], b[8];
#pragma unroll
            for (int i = 0; i < 8; i++) a[i] = As[kk][ty * 8 + i];
#pragma unroll
            for (int j = 0; j < 8; j++) b[j] = Bs[kk][tx * 8 + j];
#pragma unroll
            for (int i = 0; i < 8; i++)
#pragma unroll
                for (int j = 0; j < 8; j++) acc[i][j] = fmaf(a[i], b[j], acc[i][j]);
        }
        __syncthreads();
    }

#pragma unroll
    for (int i = 0; i < 8; i++) {
        size_t m = (size_t)(bm + ty * 8 + i);
        float* Crow = C + m * N;
        const float* addrow = add ? (add + m * N) : nullptr;
#pragma unroll
        for (int j = 0; j < 8; j++) {
            int n = bn + tx * 8 + j;
            float v = acc[i][j];
            if (bias) v += bias[n];
            if (addrow) v += addrow[n];
            Crow[n] = v;
        }
    }
}

// ---------------- prep kernels ----------------
// escore[v] = embedding[v,:] . attn_w[0, H:2H]
__global__ void k_escore(const float* __restrict__ emb, const float* __restrict__ attn_w) {
    int v = blockIdx.x;
    float s = 0.0f;
    for (int h = threadIdx.x; h < HN; h += 256) s += emb[(size_t)v * HN + h] * attn_w[HN + h];
    __shared__ float red[256];
    red[threadIdx.x] = s; __syncthreads();
    for (int off = 128; off > 0; off >>= 1) {
        if (threadIdx.x < off) red[threadIdx.x] += red[threadIdx.x + off];
        __syncthreads();
    }
    if (threadIdx.x == 0) g_escore[v] = red[0];
}

// c0s = set_h0 . attn_w[0, 0:H]
__global__ void k_c0s(const float* __restrict__ h0, const float* __restrict__ attn_w) {
    float s = 0.0f;
    for (int h = threadIdx.x; h < HN; h += 256) s += h0[h] * attn_w[h];
    __shared__ float red[256];
    red[threadIdx.x] = s; __syncthreads();
    for (int off = 128; off > 0; off >>= 1) {
        if (threadIdx.x < off) red[threadIdx.x] += red[threadIdx.x + off];
        __syncthreads();
    }
    if (threadIdx.x == 0) g_c0s[0] = red[0];
}

// out[n] = b1[n] + b2[n] + x . W[n, :K]   (K may be 0 for pure bias combine)
__global__ void k_vecproj(const float* __restrict__ x, const float* __restrict__ W,
                          const float* __restrict__ b1, const float* __restrict__ b2,
                          float* __restrict__ out, int K) {
    int n = blockIdx.x * 256 + threadIdx.x;
    if (n >= H4) return;
    float s = b1[n] + b2[n];
    const float* wr = W + (size_t)n * K;
    for (int k = 0; k < K; k++) s += x[k] * wr[k];
    out[n] = s;
}

__global__ void k_minit() {
    int i = blockIdx.x * 256 + threadIdx.x;
    if (i < BSZ) g_m[i] = 1.0f;
}

// broadcast (1,H) rows into (B,H) h and c
__global__ void k_bcast_hc(const float* __restrict__ h0, const float* __restrict__ c0) {
    int idx = blockIdx.x * 256 + threadIdx.x;
    int hh = idx & (HN - 1);
    g_h[idx] = h0[hh];
    g_c[idx] = c0[hh];
}

// ---------------- attention: r[b,:] = sum_w aw[b,w] * emb[iv[b,w],:] ----------------
__global__ void k_attn(const int* __restrict__ input_var, const float* __restrict__ input_mask,
                       const float* __restrict__ emb, const float* __restrict__ attn_b) {
    int b = blockIdx.x;
    __shared__ float aw[64];
    __shared__ int iv[64];
    int t = threadIdx.x;
    if (t < WN) {
        int tok = input_var[b * WN + t];
        iv[t] = tok;
        float s = sigf(g_c0s[0] + g_escore[tok] + attn_b[0]);
        aw[t] = s * input_mask[t * BSZ + b];
    }
    __syncthreads();
    for (int h = t; h < HN; h += 256) {
        float acc = 0.0f;
        for (int w = 0; w < WN; w++) acc += aw[w] * emb[(size_t)iv[w] * HN + h];
        g_r[(size_t)b * HN + h] = acc;
    }
}

// ---------------- LSTM pointwise (gate order: i, f, g, o) ----------------
__global__ void k_lstm_pw(const float* __restrict__ cprev, int cstride, int dec_t) {
    int idx = blockIdx.x * 256 + threadIdx.x;  // < B*H
    int b = idx >> 10, hh = idx & (HN - 1);
    const float* gr = g_gates + ((size_t)b << 12);
    float gi = sigf(gr[hh]);
    float gf = sigf(gr[HN + hh]);
    float gg = tanhf(gr[2 * HN + hh]);
    float go = sigf(gr[3 * HN + hh]);
    float cp = cprev[(size_t)b * cstride + hh];
    float cn = gf * cp + gi * gg;
    float hn = go * tanhf(cn);
    g_c[idx] = cn;
    g_h[idx] = hn;
    if (dec_t >= 0) g_dech[(size_t)dec_t * BSZ * HN + idx] = hn;
}

// masked update for message encoder: h = mt*nh + (1-mt)*h, same for c
__global__ void k_lstm_pw_masked(int t) {
    int idx = blockIdx.x * 256 + threadIdx.x;
    int b = idx >> 10, hh = idx & (HN - 1);
    const float* gr = g_gates + ((size_t)b << 12);
    float gi = sigf(gr[hh]);
    float gf = sigf(gr[HN + hh]);
    float gg = tanhf(gr[2 * HN + hh]);
    float go = sigf(gr[3 * HN + hh]);
    float cp = g_c[idx];
    float hp = g_h[idx];
    float cn = gf * cp + gi * gg;
    float hn = go * tanhf(cn);
    float mt = g_msgmask[t * BSZ + b];
    g_c[idx] = mt * cn + (1.0f - mt) * cp;
    g_h[idx] = mt * hn + (1.0f - mt) * hp;
}

// ---------------- gen output head + softmax + mask update (fused) ----------------
__global__ void k_genout(const float* __restrict__ outW, const float* __restrict__ outb, int t) {
    int b = blockIdx.x;
    __shared__ float hs[HN];
    __shared__ float sl[MVN];
    int tid = threadIdx.x;
    const float* hr = g_h + (size_t)b * HN;
    ((float4*)hs)[tid] = ((const float4*)hr)[tid];  // 256 threads * 4 = 1024
    __syncthreads();
    int warp = tid >> 5, lane = tid & 31;
#pragma unroll
    for (int j = 0; j < 8; j++) {
        int n = warp * 8 + j;
        const float* wr = outW + (size_t)n * HN;
        float s = 0.0f;
        for (int k = lane; k < HN; k += 32) s += hs[k] * wr[k];
#pragma unroll
        for (int off = 16; off > 0; off >>= 1) s += __shfl_down_sync(0xffffffffu, s, off);
        if (lane == 0) sl[n] = s + outb[n];
    }
    __syncthreads();
    if (warp == 0) {
        float x0 = sl[lane], x1 = sl[lane + 32];
        float mx = fmaxf(x0, x1);
#pragma unroll
        for (int off = 16; off > 0; off >>= 1) mx = fmaxf(mx, __shfl_xor_sync(0xffffffffu, mx, off));
        float e0 = expf(x0 - mx), e1 = expf(x1 - mx);
        float sum = e0 + e1;
#pragma unroll
        for (int off = 16; off > 0; off >>= 1) sum += __shfl_xor_sync(0xffffffffu, sum, off);
        float inv = 1.0f / sum;
        float p0 = e0 * inv, p1 = e1 * inv;
        float* mrow = g_message + ((size_t)t * BSZ + b) * MVN;
        mrow[lane] = p0;
        mrow[lane + 32] = p1;
        float peos = __shfl_sync(0xffffffffu, p0, EOS);  // EOS index 1 lives in lane 1's p0
        if (lane == 0) {
            float mold = g_m[b];
            g_msgmask[t * BSZ + b] = mold;
            g_m[b] = mold * (1.0f - peos);
        }
    }
}

// ---------------- decoder input embedding gather ----------------
__global__ void k_decx(const int* __restrict__ target_var, const float* __restrict__ emb) {
    size_t idx = (size_t)blockIdx.x * 256 + threadIdx.x;  // < T*B*H
    int hh = (int)(idx & (HN - 1));
    size_t tb = idx >> 10;
    int b = (int)(tb & (BSZ - 1));
    int tt = (int)(tb >> 9);
    int tok = (tt == 0) ? SOS : target_var[(tt - 1) * BSZ + b];
    g_decx[idx] = emb[(size_t)tok * HN + hh];
}

// ---------------- host orchestration ----------------
extern "C" void kernel_launch(void* const* d_in, const int* in_sizes, int n_in,
                              void* d_out, int out_size) {
    // defensive index shift in case target_max_len scalar is not materialized as an input
    int s = (n_in == 32) ? 0 : -1;
#define DIN(i) (d_in[(i) + (((i) >= 3) ? s : 0) + (((i) == 3 && s == -1) ? 1 : 0)])
    const int*   input_var  = (const int*)d_in[0];
    const float* input_mask = (const float*)d_in[1];
    const int*   target_var = (const int*)d_in[2];
    const float* embedding  = (const float*)d_in[4 + s];
    const float* attn_w     = (const float*)d_in[5 + s];
    const float* attn_b     = (const float*)d_in[6 + s];
    const float* set_Wih    = (const float*)d_in[7 + s];
    const float* set_Whh    = (const float*)d_in[8 + s];
    const float* set_bih    = (const float*)d_in[9 + s];
    const float* set_bhh    = (const float*)d_in[10 + s];
    const float* set_h0     = (const float*)d_in[11 + s];
    const float* set_c0     = (const float*)d_in[12 + s];
    const float* gen_x0     = (const float*)d_in[13 + s];
    const float* gen_Wih    = (const float*)d_in[14 + s];
    const float* gen_Whh    = (const float*)d_in[15 + s];
    const float* gen_bih    = (const float*)d_in[16 + s];
    const float* gen_bhh    = (const float*)d_in[17 + s];
    const float* gen_outW   = (const float*)d_in[18 + s];
    const float* gen_outb   = (const float*)d_in[19 + s];
    const float* menc_Wih   = (const float*)d_in[20 + s];
    const float* menc_Whh   = (const float*)d_in[21 + s];
    const float* menc_bih   = (const float*)d_in[22 + s];
    const float* menc_bhh   = (const float*)d_in[23 + s];
    const float* menc_h0    = (const float*)d_in[24 + s];
    const float* menc_c0    = (const float*)d_in[25 + s];
    const float* dec_Wih    = (const float*)d_in[26 + s];
    const float* dec_Whh    = (const float*)d_in[27 + s];
    const float* dec_bih    = (const float*)d_in[28 + s];
    const float* dec_bhh    = (const float*)d_in[29 + s];
    const float* dec_outW   = (const float*)d_in[30 + s];
    const float* dec_outb   = (const float*)d_in[31 + s];

    float *p_r, *p_h, *p_gates, *p_sethb, *p_genxb, *p_mencbias, *p_decbias;
    float *p_mencxb, *p_message, *p_decx, *p_decxb, *p_dech, *p_c;
    cudaGetSymbolAddress((void**)&p_r, g_r);
    cudaGetSymbolAddress((void**)&p_h, g_h);
    cudaGetSymbolAddress((void**)&p_c, g_c);
    cudaGetSymbolAddress((void**)&p_gates, g_gates);
    cudaGetSymbolAddress((void**)&p_sethb, g_sethb);
    cudaGetSymbolAddress((void**)&p_genxb, g_genxb);
    cudaGetSymbolAddress((void**)&p_mencbias, g_mencbias);
    cudaGetSymbolAddress((void**)&p_decbias, g_decbias);
    cudaGetSymbolAddress((void**)&p_mencxb, g_mencxb);
    cudaGetSymbolAddress((void**)&p_message, g_message);
    cudaGetSymbolAddress((void**)&p_decx, g_decx);
    cudaGetSymbolAddress((void**)&p_decxb, g_decxb);
    cudaGetSymbolAddress((void**)&p_dech, g_dech);

    const int BH_BLKS = (BSZ * HN) / 256;  // 2048

    // ---- prep ----
    k_escore<<<VN, 256>>>(embedding, attn_w);
    k_c0s<<<1, 256>>>(set_h0, attn_w);
    k_vecproj<<<16, 256>>>(set_h0, set_Whh, set_bih, set_bhh, p_sethb, HN);
    k_vecproj<<<16, 256>>>(gen_x0, gen_Wih, gen_bih, gen_bhh, p_genxb, MVN);
    k_vecproj<<<16, 256>>>(set_h0, set_Whh, menc_bih, menc_bhh, p_mencbias, 0);
    k_vecproj<<<16, 256>>>(set_h0, set_Whh, dec_bih, dec_bhh, p_decbias, 0);
    k_minit<<<2, 256>>>();

    // ---- attention + encoder single step ----
    k_attn<<<BSZ, 256>>>(input_var, input_mask, embedding, attn_b);
    k_gemm<<<dim3(H4 / 128, BSZ / 128), 256>>>(p_r, set_Wih, p_sethb, nullptr, p_gates, BSZ, H4, HN);
    k_lstm_pw<<<BH_BLKS, 256>>>(set_c0, 0, -1);  // cprev broadcast of set_c0

    // ---- gen loop (input projection constant -> folded into genxb) ----
    for (int t = 0; t < LN; t++) {
        k_gemm<<<dim3(H4 / 128, BSZ / 128), 256>>>(p_h, gen_Whh, p_genxb, nullptr, p_gates, BSZ, H4, HN);
        k_lstm_pw<<<BH_BLKS, 256>>>(p_c, HN, -1);
        k_genout<<<BSZ, 256>>>(gen_outW, gen_outb, t);
    }

    // ---- message encoder: batched input projection, then recurrent loop ----
    k_bcast_hc<<<BH_BLKS, 256>>>(menc_h0, menc_c0);
    k_gemm<<<dim3(H4 / 128, (LN * BSZ) / 128), 256>>>(p_message, menc_Wih, p_mencbias, nullptr,
                                                      p_mencxb, LN * BSZ, H4, MVN);
    for (int t = 0; t < LN; t++) {
        k_gemm<<<dim3(H4 / 128, BSZ / 128), 256>>>(p_h, menc_Whh, nullptr,
                                                   p_mencxb + (size_t)t * BSZ * H4, p_gates, BSZ, H4, HN);
        k_lstm_pw_masked<<<BH_BLKS, 256>>>(t);
    }

    // ---- decoder: batched input projection, recurrent loop, batched output head ----
    k_decx<<<(TN * BSZ * HN) / 256, 256>>>(target_var, embedding);
    k_gemm<<<dim3(H4 / 128, (TN * BSZ) / 128), 256>>>(p_decx, dec_Wih, p_decbias, nullptr,
                                                      p_decxb, TN * BSZ, H4, HN);
    for (int t = 0; t < TN; t++) {
        k_gemm<<<dim3(H4 / 128, BSZ / 128), 256>>>(p_h, dec_Whh, nullptr,
                                                   p_decxb + (size_t)t * BSZ * H4, p_gates, BSZ, H4, HN);
        k_lstm_pw<<<BH_BLKS, 256>>>(p_c, HN, t);
    }
    k_gemm<<<dim3(VN / 128, (TN * BSZ) / 128), 256>>>(p_dech, dec_outW, dec_outb, nullptr,
                                                      (float*)d_out, TN * BSZ, VN, HN);
}

// round 4
// speedup vs baseline: 2.7337x; 2.7337x over previous
#include <cuda_runtime.h>
#include <cstdint>

// ---------------- problem constants ----------------
#define BSZ 512
#define WN  50
#define TN  50
#define HN  1024
#define H4  4096
#define VN  1024
#define MVN 64
#define LN  30
#define SOS 0
#define EOS 1

// ---------------- device scratch ----------------
__device__ float g_escore[VN];
__device__ float g_c0s[1];
__device__ float g_r[BSZ * HN];
__device__ float g_h[BSZ * HN];
__device__ float g_c[BSZ * HN];
__device__ float g_gates[BSZ * H4];
__device__ float g_m[BSZ];
__device__ float g_message[LN * BSZ * MVN];
__device__ float g_msgmask[LN * BSZ];
__device__ float g_genxb[H4];
__device__ float g_sethb[H4];
__device__ float g_mencbias[H4];
__device__ float g_decbias[H4];
__device__ float g_mencxb[(size_t)LN * BSZ * H4];
__device__ float g_decx[(size_t)TN * BSZ * HN];
__device__ float g_decxb[(size_t)TN * BSZ * H4];
__device__ float g_dech[(size_t)TN * BSZ * HN];

__device__ __forceinline__ float sigf(float x) { return 1.0f / (1.0f + expf(-x)); }

__device__ __forceinline__ uint32_t f2tf(float f) {
    uint32_t r; asm("cvt.rna.tf32.f32 %0, %1;" : "=r"(r) : "f"(f)); return r;
}

__device__ __forceinline__ void mma_tf32(float* c, uint32_t a0, uint32_t a1, uint32_t a2,
                                         uint32_t a3, uint32_t b0, uint32_t b1) {
    asm volatile(
        "mma.sync.aligned.m16n8k8.row.col.f32.tf32.tf32.f32 "
        "{%0,%1,%2,%3}, {%4,%5,%6,%7}, {%8,%9}, {%0,%1,%2,%3};\n"
        : "+f"(c[0]), "+f"(c[1]), "+f"(c[2]), "+f"(c[3])
        : "r"(a0), "r"(a1), "r"(a2), "r"(a3), "r"(b0), "r"(b1));
}

// ---------------- tf32 tensor-core GEMM ----------------
// C[M,N] = A[M,K] @ W[N,K]^T (+bias[n]) (+add[m,n]); M%128==0, N%128==0, K%32==0.
// 256 threads, block tile 128x128x32, warp tile 64x32, double-buffered smem.
#define BKT 32
#define TILE_U32 4096   // (BKT/8)*128*8

__global__ void __launch_bounds__(256) k_gemm_tf32(const float* __restrict__ A,
                                                   const float* __restrict__ W,
                                                   const float* __restrict__ bias,
                                                   const float* __restrict__ add,
                                                   float* __restrict__ C,
                                                   int M, int N, int K) {
    extern __shared__ uint32_t smem[];
    uint32_t* sA = smem;                   // [2][TILE_U32]
    uint32_t* sB = smem + 2 * TILE_U32;    // [2][TILE_U32]

    const int tid = threadIdx.x;
    const int lane = tid & 31;
    const int wid = tid >> 5;
    const int warp_m = wid & 1;    // 0..1 -> 64-row halves
    const int warp_n = wid >> 1;   // 0..3 -> 32-col quarters
    const int bm = blockIdx.y * 128;
    const int bn = blockIdx.x * 128;

    const int ldrow = tid >> 1;          // 0..127
    const int kg0 = (tid & 1) * 2;       // this thread's two 8-wide k-groups

    const float* Arow = A + (size_t)(bm + ldrow) * K;
    const float* Wrow = W + (size_t)(bn + ldrow) * K;

    float4 stA[2][2], stB[2][2];
    const int NT = K / BKT;

    auto LOAD = [&](int kt) {
#pragma unroll
        for (int j = 0; j < 2; j++) {
            int kb = kt * BKT + (kg0 + j) * 8;
            stA[j][0] = *(const float4*)(Arow + kb);
            stA[j][1] = *(const float4*)(Arow + kb + 4);
            stB[j][0] = *(const float4*)(Wrow + kb);
            stB[j][1] = *(const float4*)(Wrow + kb + 4);
        }
    };
    auto STS = [&](int buf) {
#pragma unroll
        for (int j = 0; j < 2; j++) {
            int kg = kg0 + j;
            uint32_t* bA = sA + buf * TILE_U32 + ((kg * 128 + ldrow) << 3);
            uint32_t* bB = sB + buf * TILE_U32 + ((kg * 128 + ldrow) << 3);
            int sw = (ldrow ^ (ldrow >> 2) ^ kg) & 3;
            const float* fa = (const float*)&stA[j][0];
            const float* fb = (const float*)&stB[j][0];
#pragma unroll
            for (int pp = 0; pp < 4; pp++) {
                int slot = (pp ^ sw) & 3;
                ((uint2*)bA)[slot] = make_uint2(f2tf(fa[pp]), f2tf(fa[pp + 4]));
                ((uint2*)bB)[slot] = make_uint2(f2tf(fb[pp]), f2tf(fb[pp + 4]));
            }
        }
    };

    float acc[4][4][4];
#pragma unroll
    for (int mt = 0; mt < 4; mt++)
#pragma unroll
        for (int nt = 0; nt < 4; nt++)
#pragma unroll
            for (int q = 0; q < 4; q++) acc[mt][nt][q] = 0.0f;

    const int g = lane >> 2, tig = lane & 3;

    LOAD(0); STS(0); __syncthreads();
    for (int kt = 0; kt < NT; kt++) {
        int cur = kt & 1;
        if (kt + 1 < NT) LOAD(kt + 1);
        const uint32_t* cA = sA + cur * TILE_U32;
        const uint32_t* cB = sB + cur * TILE_U32;
#pragma unroll
        for (int ks = 0; ks < 4; ks++) {
            uint32_t af[4][4];
#pragma unroll
            for (int mt = 0; mt < 4; mt++) {
                int r0 = warp_m * 64 + mt * 16 + g;
                int r1 = r0 + 8;
                uint2 lo = ((const uint2*)(cA + ((ks * 128 + r0) << 3)))[(tig ^ r0 ^ (r0 >> 2) ^ ks) & 3];
                uint2 hi = ((const uint2*)(cA + ((ks * 128 + r1) << 3)))[(tig ^ r1 ^ (r1 >> 2) ^ ks) & 3];
                af[mt][0] = lo.x; af[mt][1] = hi.x; af[mt][2] = lo.y; af[mt][3] = hi.y;
            }
            uint2 bf[4];
#pragma unroll
            for (int nt = 0; nt < 4; nt++) {
                int nr = warp_n * 32 + nt * 8 + g;
                bf[nt] = ((const uint2*)(cB + ((ks * 128 + nr) << 3)))[(tig ^ nr ^ (nr >> 2) ^ ks) & 3];
            }
#pragma unroll
            for (int mt = 0; mt < 4; mt++)
#pragma unroll
                for (int nt = 0; nt < 4; nt++)
                    mma_tf32(acc[mt][nt], af[mt][0], af[mt][1], af[mt][2], af[mt][3],
                             bf[nt].x, bf[nt].y);
        }
        if (kt + 1 < NT) STS(cur ^ 1);
        __syncthreads();
    }

    // epilogue
#pragma unroll
    for (int mt = 0; mt < 4; mt++) {
        int r0 = bm + warp_m * 64 + mt * 16 + g;
#pragma unroll
        for (int nt = 0; nt < 4; nt++) {
            int cn = bn + warp_n * 32 + nt * 8 + tig * 2;
            float2 v0 = make_float2(acc[mt][nt][0], acc[mt][nt][1]);
            float2 v1 = make_float2(acc[mt][nt][2], acc[mt][nt][3]);
            if (bias) {
                float b0 = bias[cn], b1 = bias[cn + 1];
                v0.x += b0; v0.y += b1; v1.x += b0; v1.y += b1;
            }
            if (add) {
                const float* a0p = add + (size_t)r0 * N + cn;
                const float* a1p = add + (size_t)(r0 + 8) * N + cn;
                v0.x += a0p[0]; v0.y += a0p[1];
                v1.x += a1p[0]; v1.y += a1p[1];
            }
            *(float2*)(C + (size_t)r0 * N + cn) = v0;
            *(float2*)(C + (size_t)(r0 + 8) * N + cn) = v1;
        }
    }
}

// ---------------- prep kernels ----------------
__global__ void k_escore(const float* __restrict__ emb, const float* __restrict__ attn_w) {
    int v = blockIdx.x;
    float s = 0.0f;
    for (int h = threadIdx.x; h < HN; h += 256) s += emb[(size_t)v * HN + h] * attn_w[HN + h];
    __shared__ float red[256];
    red[threadIdx.x] = s; __syncthreads();
    for (int off = 128; off > 0; off >>= 1) {
        if (threadIdx.x < off) red[threadIdx.x] += red[threadIdx.x + off];
        __syncthreads();
    }
    if (threadIdx.x == 0) g_escore[v] = red[0];
}

__global__ void k_c0s(const float* __restrict__ h0, const float* __restrict__ attn_w) {
    float s = 0.0f;
    for (int h = threadIdx.x; h < HN; h += 256) s += h0[h] * attn_w[h];
    __shared__ float red[256];
    red[threadIdx.x] = s; __syncthreads();
    for (int off = 128; off > 0; off >>= 1) {
        if (threadIdx.x < off) red[threadIdx.x] += red[threadIdx.x + off];
        __syncthreads();
    }
    if (threadIdx.x == 0) g_c0s[0] = red[0];
}

__global__ void k_vecproj(const float* __restrict__ x, const float* __restrict__ W,
                          const float* __restrict__ b1, const float* __restrict__ b2,
                          float* __restrict__ out, int K) {
    int n = blockIdx.x * 256 + threadIdx.x;
    if (n >= H4) return;
    float s = b1[n] + b2[n];
    const float* wr = W + (size_t)n * K;
    for (int k = 0; k < K; k++) s += x[k] * wr[k];
    out[n] = s;
}

__global__ void k_minit() {
    int i = blockIdx.x * 256 + threadIdx.x;
    if (i < BSZ) g_m[i] = 1.0f;
}

__global__ void k_bcast_hc(const float* __restrict__ h0, const float* __restrict__ c0) {
    int idx = blockIdx.x * 256 + threadIdx.x;
    int hh = idx & (HN - 1);
    g_h[idx] = h0[hh];
    g_c[idx] = c0[hh];
}

// ---------------- attention ----------------
__global__ void k_attn(const int* __restrict__ input_var, const float* __restrict__ input_mask,
                       const float* __restrict__ emb, const float* __restrict__ attn_b) {
    int b = blockIdx.x;
    __shared__ float aw[64];
    __shared__ int iv[64];
    int t = threadIdx.x;
    if (t < WN) {
        int tok = input_var[b * WN + t];
        iv[t] = tok;
        float s = sigf(g_c0s[0] + g_escore[tok] + attn_b[0]);
        aw[t] = s * input_mask[t * BSZ + b];
    }
    __syncthreads();
    for (int h = t; h < HN; h += 256) {
        float acc = 0.0f;
        for (int w = 0; w < WN; w++) acc += aw[w] * emb[(size_t)iv[w] * HN + h];
        g_r[(size_t)b * HN + h] = acc;
    }
}

// ---------------- LSTM pointwise ----------------
__global__ void k_lstm_pw(const float* __restrict__ cprev, int cstride, int dec_t) {
    int idx = blockIdx.x * 256 + threadIdx.x;
    int b = idx >> 10, hh = idx & (HN - 1);
    const float* gr = g_gates + ((size_t)b << 12);
    float gi = sigf(gr[hh]);
    float gf = sigf(gr[HN + hh]);
    float gg = tanhf(gr[2 * HN + hh]);
    float go = sigf(gr[3 * HN + hh]);
    float cp = cprev[(size_t)b * cstride + hh];
    float cn = gf * cp + gi * gg;
    float hn = go * tanhf(cn);
    g_c[idx] = cn;
    g_h[idx] = hn;
    if (dec_t >= 0) g_dech[(size_t)dec_t * BSZ * HN + idx] = hn;
}

__global__ void k_lstm_pw_masked(int t) {
    int idx = blockIdx.x * 256 + threadIdx.x;
    int b = idx >> 10, hh = idx & (HN - 1);
    const float* gr = g_gates + ((size_t)b << 12);
    float gi = sigf(gr[hh]);
    float gf = sigf(gr[HN + hh]);
    float gg = tanhf(gr[2 * HN + hh]);
    float go = sigf(gr[3 * HN + hh]);
    float cp = g_c[idx];
    float hp = g_h[idx];
    float cn = gf * cp + gi * gg;
    float hn = go * tanhf(cn);
    float mt = g_msgmask[t * BSZ + b];
    g_c[idx] = mt * cn + (1.0f - mt) * cp;
    g_h[idx] = mt * hn + (1.0f - mt) * hp;
}

// ---------------- gen output head (fused softmax + mask) ----------------
__global__ void k_genout(const float* __restrict__ outW, const float* __restrict__ outb, int t) {
    int b = blockIdx.x;
    __shared__ float hs[HN];
    __shared__ float sl[MVN];
    int tid = threadIdx.x;
    const float* hr = g_h + (size_t)b * HN;
    ((float4*)hs)[tid] = ((const float4*)hr)[tid];
    __syncthreads();
    int warp = tid >> 5, lane = tid & 31;
#pragma unroll
    for (int j = 0; j < 8; j++) {
        int n = warp * 8 + j;
        const float* wr = outW + (size_t)n * HN;
        float s = 0.0f;
        for (int k = lane; k < HN; k += 32) s += hs[k] * wr[k];
#pragma unroll
        for (int off = 16; off > 0; off >>= 1) s += __shfl_down_sync(0xffffffffu, s, off);
        if (lane == 0) sl[n] = s + outb[n];
    }
    __syncthreads();
    if (warp == 0) {
        float x0 = sl[lane], x1 = sl[lane + 32];
        float mx = fmaxf(x0, x1);
#pragma unroll
        for (int off = 16; off > 0; off >>= 1) mx = fmaxf(mx, __shfl_xor_sync(0xffffffffu, mx, off));
        float e0 = expf(x0 - mx), e1 = expf(x1 - mx);
        float sum = e0 + e1;
#pragma unroll
        for (int off = 16; off > 0; off >>= 1) sum += __shfl_xor_sync(0xffffffffu, sum, off);
        float inv = 1.0f / sum;
        float p0 = e0 * inv, p1 = e1 * inv;
        float* mrow = g_message + ((size_t)t * BSZ + b) * MVN;
        mrow[lane] = p0;
        mrow[lane + 32] = p1;
        float peos = __shfl_sync(0xffffffffu, p0, EOS);
        if (lane == 0) {
            float mold = g_m[b];
            g_msgmask[t * BSZ + b] = mold;
            g_m[b] = mold * (1.0f - peos);
        }
    }
}

// ---------------- decoder input gather ----------------
__global__ void k_decx(const int* __restrict__ target_var, const float* __restrict__ emb) {
    size_t idx = (size_t)blockIdx.x * 256 + threadIdx.x;
    int hh = (int)(idx & (HN - 1));
    size_t tb = idx >> 10;
    int b = (int)(tb & (BSZ - 1));
    int tt = (int)(tb >> 9);
    int tok = (tt == 0) ? SOS : target_var[(tt - 1) * BSZ + b];
    g_decx[idx] = emb[(size_t)tok * HN + hh];
}

// ---------------- host orchestration ----------------
extern "C" void kernel_launch(void* const* d_in, const int* in_sizes, int n_in,
                              void* d_out, int out_size) {
    int s = (n_in == 32) ? 0 : -1;
    const int*   input_var  = (const int*)d_in[0];
    const float* input_mask = (const float*)d_in[1];
    const int*   target_var = (const int*)d_in[2];
    const float* embedding  = (const float*)d_in[4 + s];
    const float* attn_w     = (const float*)d_in[5 + s];
    const float* attn_b     = (const float*)d_in[6 + s];
    const float* set_Wih    = (const float*)d_in[7 + s];
    const float* set_Whh    = (const float*)d_in[8 + s];
    const float* set_bih    = (const float*)d_in[9 + s];
    const float* set_bhh    = (const float*)d_in[10 + s];
    const float* set_h0     = (const float*)d_in[11 + s];
    const float* set_c0     = (const float*)d_in[12 + s];
    const float* gen_x0     = (const float*)d_in[13 + s];
    const float* gen_Wih    = (const float*)d_in[14 + s];
    const float* gen_Whh    = (const float*)d_in[15 + s];
    const float* gen_bih    = (const float*)d_in[16 + s];
    const float* gen_bhh    = (const float*)d_in[17 + s];
    const float* gen_outW   = (const float*)d_in[18 + s];
    const float* gen_outb   = (const float*)d_in[19 + s];
    const float* menc_Wih   = (const float*)d_in[20 + s];
    const float* menc_Whh   = (const float*)d_in[21 + s];
    const float* menc_bih   = (const float*)d_in[22 + s];
    const float* menc_bhh   = (const float*)d_in[23 + s];
    const float* menc_h0    = (const float*)d_in[24 + s];
    const float* menc_c0    = (const float*)d_in[25 + s];
    const float* dec_Wih    = (const float*)d_in[26 + s];
    const float* dec_Whh    = (const float*)d_in[27 + s];
    const float* dec_bih    = (const float*)d_in[28 + s];
    const float* dec_bhh    = (const float*)d_in[29 + s];
    const float* dec_outW   = (const float*)d_in[30 + s];
    const float* dec_outb   = (const float*)d_in[31 + s];

    float *p_r, *p_h, *p_c, *p_gates, *p_sethb, *p_genxb, *p_mencbias, *p_decbias;
    float *p_mencxb, *p_message, *p_decx, *p_decxb, *p_dech;
    cudaGetSymbolAddress((void**)&p_r, g_r);
    cudaGetSymbolAddress((void**)&p_h, g_h);
    cudaGetSymbolAddress((void**)&p_c, g_c);
    cudaGetSymbolAddress((void**)&p_gates, g_gates);
    cudaGetSymbolAddress((void**)&p_sethb, g_sethb);
    cudaGetSymbolAddress((void**)&p_genxb, g_genxb);
    cudaGetSymbolAddress((void**)&p_mencbias, g_mencbias);
    cudaGetSymbolAddress((void**)&p_decbias, g_decbias);
    cudaGetSymbolAddress((void**)&p_mencxb, g_mencxb);
    cudaGetSymbolAddress((void**)&p_message, g_message);
    cudaGetSymbolAddress((void**)&p_decx, g_decx);
    cudaGetSymbolAddress((void**)&p_decxb, g_decxb);
    cudaGetSymbolAddress((void**)&p_dech, g_dech);

    const int SMEM_GEMM = 4 * TILE_U32 * (int)sizeof(uint32_t);  // 64 KB
    cudaFuncSetAttribute(k_gemm_tf32, cudaFuncAttributeMaxDynamicSharedMemorySize, SMEM_GEMM);

    const int BH_BLKS = (BSZ * HN) / 256;

    // ---- prep ----
    k_escore<<<VN, 256>>>(embedding, attn_w);
    k_c0s<<<1, 256>>>(set_h0, attn_w);
    k_vecproj<<<16, 256>>>(set_h0, set_Whh, set_bih, set_bhh, p_sethb, HN);
    k_vecproj<<<16, 256>>>(gen_x0, gen_Wih, gen_bih, gen_bhh, p_genxb, MVN);
    k_vecproj<<<16, 256>>>(set_h0, set_Whh, menc_bih, menc_bhh, p_mencbias, 0);
    k_vecproj<<<16, 256>>>(set_h0, set_Whh, dec_bih, dec_bhh, p_decbias, 0);
    k_minit<<<2, 256>>>();

    // ---- attention + encoder step ----
    k_attn<<<BSZ, 256>>>(input_var, input_mask, embedding, attn_b);
    k_gemm_tf32<<<dim3(H4 / 128, BSZ / 128), 256, SMEM_GEMM>>>(p_r, set_Wih, p_sethb, nullptr,
                                                               p_gates, BSZ, H4, HN);
    k_lstm_pw<<<BH_BLKS, 256>>>(set_c0, 0, -1);

    // ---- gen loop ----
    for (int t = 0; t < LN; t++) {
        k_gemm_tf32<<<dim3(H4 / 128, BSZ / 128), 256, SMEM_GEMM>>>(p_h, gen_Whh, p_genxb, nullptr,
                                                                   p_gates, BSZ, H4, HN);
        k_lstm_pw<<<BH_BLKS, 256>>>(p_c, HN, -1);
        k_genout<<<BSZ, 256>>>(gen_outW, gen_outb, t);
    }

    // ---- message encoder ----
    k_bcast_hc<<<BH_BLKS, 256>>>(menc_h0, menc_c0);
    k_gemm_tf32<<<dim3(H4 / 128, (LN * BSZ) / 128), 256, SMEM_GEMM>>>(
        p_message, menc_Wih, p_mencbias, nullptr, p_mencxb, LN * BSZ, H4, MVN);
    for (int t = 0; t < LN; t++) {
        k_gemm_tf32<<<dim3(H4 / 128, BSZ / 128), 256, SMEM_GEMM>>>(
            p_h, menc_Whh, nullptr, p_mencxb + (size_t)t * BSZ * H4, p_gates, BSZ, H4, HN);
        k_lstm_pw_masked<<<BH_BLKS, 256>>>(t);
    }

    // ---- decoder ----
    k_decx<<<(TN * BSZ * HN) / 256, 256>>>(target_var, embedding);
    k_gemm_tf32<<<dim3(H4 / 128, (TN * BSZ) / 128), 256, SMEM_GEMM>>>(
        p_decx, dec_Wih, p_decbias, nullptr, p_decxb, TN * BSZ, H4, HN);
    for (int t = 0; t < TN; t++) {
        k_gemm_tf32<<<dim3(H4 / 128, BSZ / 128), 256, SMEM_GEMM>>>(
            p_h, dec_Whh, nullptr, p_decxb + (size_t)t * BSZ * H4, p_gates, BSZ, H4, HN);
        k_lstm_pw<<<BH_BLKS, 256>>>(p_c, HN, t);
    }
    k_gemm_tf32<<<dim3(VN / 128, (TN * BSZ) / 128), 256, SMEM_GEMM>>>(
        p_dech, dec_outW, dec_outb, nullptr, (float*)d_out, TN * BSZ, VN, HN);
}

// round 5
// speedup vs baseline: 2.7555x; 1.0080x over previous
#include <cuda_runtime.h>
#include <cstdint>

// ---------------- problem constants ----------------
#define BSZ 512
#define WN  50
#define TN  50
#define HN  1024
#define H4  4096
#define VN  1024
#define MVN 64
#define LN  30
#define SOS 0
#define EOS 1

// ---------------- device scratch ----------------
__device__ float g_escore[VN];
__device__ float g_c0s[1];
__device__ float g_r[BSZ * HN];
__device__ float g_h[BSZ * HN];
__device__ float g_c[BSZ * HN];
__device__ float g_gates[BSZ * H4];
__device__ float g_m[BSZ];
__device__ float g_message[LN * BSZ * MVN];
__device__ float g_msgmask[LN * BSZ];
__device__ float g_genxb[H4];
__device__ float g_sethb[H4];
__device__ float g_mencbias[H4];
__device__ float g_decbias[H4];
__device__ float g_mencxb[(size_t)LN * BSZ * H4];
__device__ float g_decx[(size_t)TN * BSZ * HN];
__device__ float g_decxb[(size_t)TN * BSZ * H4];
__device__ float g_dech[(size_t)TN * BSZ * HN];

__device__ __forceinline__ float sigf(float x) { return 1.0f / (1.0f + expf(-x)); }

__device__ __forceinline__ uint32_t f2tf(float f) {
    uint32_t r; asm("cvt.rna.tf32.f32 %0, %1;" : "=r"(r) : "f"(f)); return r;
}

__device__ __forceinline__ void mma_tf32(float* c, uint32_t a0, uint32_t a1, uint32_t a2,
                                         uint32_t a3, uint32_t b0, uint32_t b1) {
    asm volatile(
        "mma.sync.aligned.m16n8k8.row.col.f32.tf32.tf32.f32 "
        "{%0,%1,%2,%3}, {%4,%5,%6,%7}, {%8,%9}, {%0,%1,%2,%3};\n"
        : "+f"(c[0]), "+f"(c[1]), "+f"(c[2]), "+f"(c[3])
        : "r"(a0), "r"(a1), "r"(a2), "r"(a3), "r"(b0), "r"(b1));
}

// ---------------- tf32 tensor-core GEMM ----------------
// C[M,N] = A[M,K] @ W[N,K]^T (+bias[n]) (+add[m,n]); M%128==0, N%128==0, K%32==0.
// 256 threads, block tile 128x128x32, warp tile 64x32, double-buffered smem.
#define BKT 32
#define TILE_U32 4096   // (BKT/8)*128*8

__global__ void __launch_bounds__(256) k_gemm_tf32(const float* __restrict__ A,
                                                   const float* __restrict__ W,
                                                   const float* __restrict__ bias,
                                                   const float* __restrict__ add,
                                                   float* __restrict__ C,
                                                   int M, int N, int K) {
    extern __shared__ uint32_t smem[];
    uint32_t* sA = smem;                   // [2][TILE_U32]
    uint32_t* sB = smem + 2 * TILE_U32;    // [2][TILE_U32]

    const int tid = threadIdx.x;
    const int lane = tid & 31;
    const int wid = tid >> 5;
    const int warp_m = wid & 1;    // 0..1 -> 64-row halves
    const int warp_n = wid >> 1;   // 0..3 -> 32-col quarters
    const int bm = blockIdx.y * 128;
    const int bn = blockIdx.x * 128;

    const int ldrow = tid >> 1;          // 0..127
    const int kg0 = (tid & 1) * 2;       // this thread's two 8-wide k-groups

    const float* Arow = A + (size_t)(bm + ldrow) * K;
    const float* Wrow = W + (size_t)(bn + ldrow) * K;

    float4 stA[2][2], stB[2][2];
    const int NT = K / BKT;

    auto LOAD = [&](int kt) {
#pragma unroll
        for (int j = 0; j < 2; j++) {
            int kb = kt * BKT + (kg0 + j) * 8;
            stA[j][0] = *(const float4*)(Arow + kb);
            stA[j][1] = *(const float4*)(Arow + kb + 4);
            stB[j][0] = *(const float4*)(Wrow + kb);
            stB[j][1] = *(const float4*)(Wrow + kb + 4);
        }
    };
    auto STS = [&](int buf) {
#pragma unroll
        for (int j = 0; j < 2; j++) {
            int kg = kg0 + j;
            uint32_t* bA = sA + buf * TILE_U32 + ((kg * 128 + ldrow) << 3);
            uint32_t* bB = sB + buf * TILE_U32 + ((kg * 128 + ldrow) << 3);
            int sw = (ldrow ^ (ldrow >> 2) ^ kg) & 3;
            const float* fa = (const float*)&stA[j][0];
            const float* fb = (const float*)&stB[j][0];
#pragma unroll
            for (int pp = 0; pp < 4; pp++) {
                int slot = (pp ^ sw) & 3;
                ((uint2*)bA)[slot] = make_uint2(f2tf(fa[pp]), f2tf(fa[pp + 4]));
                ((uint2*)bB)[slot] = make_uint2(f2tf(fb[pp]), f2tf(fb[pp + 4]));
            }
        }
    };

    float acc[4][4][4];
#pragma unroll
    for (int mt = 0; mt < 4; mt++)
#pragma unroll
        for (int nt = 0; nt < 4; nt++)
#pragma unroll
            for (int q = 0; q < 4; q++) acc[mt][nt][q] = 0.0f;

    const int g = lane >> 2, tig = lane & 3;

    LOAD(0); STS(0); __syncthreads();
    for (int kt = 0; kt < NT; kt++) {
        int cur = kt & 1;
        if (kt + 1 < NT) LOAD(kt + 1);
        const uint32_t* cA = sA + cur * TILE_U32;
        const uint32_t* cB = sB + cur * TILE_U32;
#pragma unroll
        for (int ks = 0; ks < 4; ks++) {
            uint32_t af[4][4];
#pragma unroll
            for (int mt = 0; mt < 4; mt++) {
                int r0 = warp_m * 64 + mt * 16 + g;
                int r1 = r0 + 8;
                uint2 lo = ((const uint2*)(cA + ((ks * 128 + r0) << 3)))[(tig ^ r0 ^ (r0 >> 2) ^ ks) & 3];
                uint2 hi = ((const uint2*)(cA + ((ks * 128 + r1) << 3)))[(tig ^ r1 ^ (r1 >> 2) ^ ks) & 3];
                af[mt][0] = lo.x; af[mt][1] = hi.x; af[mt][2] = lo.y; af[mt][3] = hi.y;
            }
            uint2 bf[4];
#pragma unroll
            for (int nt = 0; nt < 4; nt++) {
                int nr = warp_n * 32 + nt * 8 + g;
                bf[nt] = ((const uint2*)(cB + ((ks * 128 + nr) << 3)))[(tig ^ nr ^ (nr >> 2) ^ ks) & 3];
            }
#pragma unroll
            for (int mt = 0; mt < 4; mt++)
#pragma unroll
                for (int nt = 0; nt < 4; nt++)
                    mma_tf32(acc[mt][nt], af[mt][0], af[mt][1], af[mt][2], af[mt][3],
                             bf[nt].x, bf[nt].y);
        }
        if (kt + 1 < NT) STS(cur ^ 1);
        __syncthreads();
    }

    // epilogue
#pragma unroll
    for (int mt = 0; mt < 4; mt++) {
        int r0 = bm + warp_m * 64 + mt * 16 + g;
#pragma unroll
        for (int nt = 0; nt < 4; nt++) {
            int cn = bn + warp_n * 32 + nt * 8 + tig * 2;
            float2 v0 = make_float2(acc[mt][nt][0], acc[mt][nt][1]);
            float2 v1 = make_float2(acc[mt][nt][2], acc[mt][nt][3]);
            if (bias) {
                float b0 = bias[cn], b1 = bias[cn + 1];
                v0.x += b0; v0.y += b1; v1.x += b0; v1.y += b1;
            }
            if (add) {
                const float* a0p = add + (size_t)r0 * N + cn;
                const float* a1p = add + (size_t)(r0 + 8) * N + cn;
                v0.x += a0p[0]; v0.y += a0p[1];
                v1.x += a1p[0]; v1.y += a1p[1];
            }
            *(float2*)(C + (size_t)r0 * N + cn) = v0;
            *(float2*)(C + (size_t)(r0 + 8) * N + cn) = v1;
        }
    }
}

// ---------------- prep kernels ----------------
__global__ void k_escore(const float* __restrict__ emb, const float* __restrict__ attn_w) {
    int v = blockIdx.x;
    float s = 0.0f;
    for (int h = threadIdx.x; h < HN; h += 256) s += emb[(size_t)v * HN + h] * attn_w[HN + h];
    __shared__ float red[256];
    red[threadIdx.x] = s; __syncthreads();
    for (int off = 128; off > 0; off >>= 1) {
        if (threadIdx.x < off) red[threadIdx.x] += red[threadIdx.x + off];
        __syncthreads();
    }
    if (threadIdx.x == 0) g_escore[v] = red[0];
}

__global__ void k_c0s(const float* __restrict__ h0, const float* __restrict__ attn_w) {
    float s = 0.0f;
    for (int h = threadIdx.x; h < HN; h += 256) s += h0[h] * attn_w[h];
    __shared__ float red[256];
    red[threadIdx.x] = s; __syncthreads();
    for (int off = 128; off > 0; off >>= 1) {
        if (threadIdx.x < off) red[threadIdx.x] += red[threadIdx.x + off];
        __syncthreads();
    }
    if (threadIdx.x == 0) g_c0s[0] = red[0];
}

__global__ void k_vecproj(const float* __restrict__ x, const float* __restrict__ W,
                          const float* __restrict__ b1, const float* __restrict__ b2,
                          float* __restrict__ out, int K) {
    int n = blockIdx.x * 256 + threadIdx.x;
    if (n >= H4) return;
    float s = b1[n] + b2[n];
    const float* wr = W + (size_t)n * K;
    for (int k = 0; k < K; k++) s += x[k] * wr[k];
    out[n] = s;
}

__global__ void k_minit() {
    int i = blockIdx.x * 256 + threadIdx.x;
    if (i < BSZ) g_m[i] = 1.0f;
}

__global__ void k_bcast_hc(const float* __restrict__ h0, const float* __restrict__ c0) {
    int idx = blockIdx.x * 256 + threadIdx.x;
    int hh = idx & (HN - 1);
    g_h[idx] = h0[hh];
    g_c[idx] = c0[hh];
}

// ---------------- attention ----------------
__global__ void k_attn(const int* __restrict__ input_var, const float* __restrict__ input_mask,
                       const float* __restrict__ emb, const float* __restrict__ attn_b) {
    int b = blockIdx.x;
    __shared__ float aw[64];
    __shared__ int iv[64];
    int t = threadIdx.x;
    if (t < WN) {
        int tok = input_var[b * WN + t];
        iv[t] = tok;
        float s = sigf(g_c0s[0] + g_escore[tok] + attn_b[0]);
        aw[t] = s * input_mask[t * BSZ + b];
    }
    __syncthreads();
    for (int h = t; h < HN; h += 256) {
        float acc = 0.0f;
        for (int w = 0; w < WN; w++) acc += aw[w] * emb[(size_t)iv[w] * HN + h];
        g_r[(size_t)b * HN + h] = acc;
    }
}

// ---------------- LSTM pointwise ----------------
__global__ void k_lstm_pw(const float* __restrict__ cprev, int cstride, int dec_t) {
    int idx = blockIdx.x * 256 + threadIdx.x;
    int b = idx >> 10, hh = idx & (HN - 1);
    const float* gr = g_gates + ((size_t)b << 12);
    float gi = sigf(gr[hh]);
    float gf = sigf(gr[HN + hh]);
    float gg = tanhf(gr[2 * HN + hh]);
    float go = sigf(gr[3 * HN + hh]);
    float cp = cprev[(size_t)b * cstride + hh];
    float cn = gf * cp + gi * gg;
    float hn = go * tanhf(cn);
    g_c[idx] = cn;
    g_h[idx] = hn;
    if (dec_t >= 0) g_dech[(size_t)dec_t * BSZ * HN + idx] = hn;
}

__global__ void k_lstm_pw_masked(int t) {
    int idx = blockIdx.x * 256 + threadIdx.x;
    int b = idx >> 10, hh = idx & (HN - 1);
    const float* gr = g_gates + ((size_t)b << 12);
    float gi = sigf(gr[hh]);
    float gf = sigf(gr[HN + hh]);
    float gg = tanhf(gr[2 * HN + hh]);
    float go = sigf(gr[3 * HN + hh]);
    float cp = g_c[idx];
    float hp = g_h[idx];
    float cn = gf * cp + gi * gg;
    float hn = go * tanhf(cn);
    float mt = g_msgmask[t * BSZ + b];
    g_c[idx] = mt * cn + (1.0f - mt) * cp;
    g_h[idx] = mt * hn + (1.0f - mt) * hp;
}

// ---------------- gen output head (fused softmax + mask) ----------------
__global__ void k_genout(const float* __restrict__ outW, const float* __restrict__ outb, int t) {
    int b = blockIdx.x;
    __shared__ float hs[HN];
    __shared__ float sl[MVN];
    int tid = threadIdx.x;
    const float* hr = g_h + (size_t)b * HN;
    ((float4*)hs)[tid] = ((const float4*)hr)[tid];
    __syncthreads();
    int warp = tid >> 5, lane = tid & 31;
#pragma unroll
    for (int j = 0; j < 8; j++) {
        int n = warp * 8 + j;
        const float* wr = outW + (size_t)n * HN;
        float s = 0.0f;
        for (int k = lane; k < HN; k += 32) s += hs[k] * wr[k];
#pragma unroll
        for (int off = 16; off > 0; off >>= 1) s += __shfl_down_sync(0xffffffffu, s, off);
        if (lane == 0) sl[n] = s + outb[n];
    }
    __syncthreads();
    if (warp == 0) {
        float x0 = sl[lane], x1 = sl[lane + 32];
        float mx = fmaxf(x0, x1);
#pragma unroll
        for (int off = 16; off > 0; off >>= 1) mx = fmaxf(mx, __shfl_xor_sync(0xffffffffu, mx, off));
        float e0 = expf(x0 - mx), e1 = expf(x1 - mx);
        float sum = e0 + e1;
#pragma unroll
        for (int off = 16; off > 0; off >>= 1) sum += __shfl_xor_sync(0xffffffffu, sum, off);
        float inv = 1.0f / sum;
        float p0 = e0 * inv, p1 = e1 * inv;
        float* mrow = g_message + ((size_t)t * BSZ + b) * MVN;
        mrow[lane] = p0;
        mrow[lane + 32] = p1;
        float peos = __shfl_sync(0xffffffffu, p0, EOS);
        if (lane == 0) {
            float mold = g_m[b];
            g_msgmask[t * BSZ + b] = mold;
            g_m[b] = mold * (1.0f - peos);
        }
    }
}

// ---------------- decoder input gather ----------------
__global__ void k_decx(const int* __restrict__ target_var, const float* __restrict__ emb) {
    size_t idx = (size_t)blockIdx.x * 256 + threadIdx.x;
    int hh = (int)(idx & (HN - 1));
    size_t tb = idx >> 10;
    int b = (int)(tb & (BSZ - 1));
    int tt = (int)(tb >> 9);
    int tok = (tt == 0) ? SOS : target_var[(tt - 1) * BSZ + b];
    g_decx[idx] = emb[(size_t)tok * HN + hh];
}

// ---------------- host orchestration ----------------
extern "C" void kernel_launch(void* const* d_in, const int* in_sizes, int n_in,
                              void* d_out, int out_size) {
    int s = (n_in == 32) ? 0 : -1;
    const int*   input_var  = (const int*)d_in[0];
    const float* input_mask = (const float*)d_in[1];
    const int*   target_var = (const int*)d_in[2];
    const float* embedding  = (const float*)d_in[4 + s];
    const float* attn_w     = (const float*)d_in[5 + s];
    const float* attn_b     = (const float*)d_in[6 + s];
    const float* set_Wih    = (const float*)d_in[7 + s];
    const float* set_Whh    = (const float*)d_in[8 + s];
    const float* set_bih    = (const float*)d_in[9 + s];
    const float* set_bhh    = (const float*)d_in[10 + s];
    const float* set_h0     = (const float*)d_in[11 + s];
    const float* set_c0     = (const float*)d_in[12 + s];
    const float* gen_x0     = (const float*)d_in[13 + s];
    const float* gen_Wih    = (const float*)d_in[14 + s];
    const float* gen_Whh    = (const float*)d_in[15 + s];
    const float* gen_bih    = (const float*)d_in[16 + s];
    const float* gen_bhh    = (const float*)d_in[17 + s];
    const float* gen_outW   = (const float*)d_in[18 + s];
    const float* gen_outb   = (const float*)d_in[19 + s];
    const float* menc_Wih   = (const float*)d_in[20 + s];
    const float* menc_Whh   = (const float*)d_in[21 + s];
    const float* menc_bih   = (const float*)d_in[22 + s];
    const float* menc_bhh   = (const float*)d_in[23 + s];
    const float* menc_h0    = (const float*)d_in[24 + s];
    const float* menc_c0    = (const float*)d_in[25 + s];
    const float* dec_Wih    = (const float*)d_in[26 + s];
    const float* dec_Whh    = (const float*)d_in[27 + s];
    const float* dec_bih    = (const float*)d_in[28 + s];
    const float* dec_bhh    = (const float*)d_in[29 + s];
    const float* dec_outW   = (const float*)d_in[30 + s];
    const float* dec_outb   = (const float*)d_in[31 + s];

    float *p_r, *p_h, *p_c, *p_gates, *p_sethb, *p_genxb, *p_mencbias, *p_decbias;
    float *p_mencxb, *p_message, *p_decx, *p_decxb, *p_dech;
    cudaGetSymbolAddress((void**)&p_r, g_r);
    cudaGetSymbolAddress((void**)&p_h, g_h);
    cudaGetSymbolAddress((void**)&p_c, g_c);
    cudaGetSymbolAddress((void**)&p_gates, g_gates);
    cudaGetSymbolAddress((void**)&p_sethb, g_sethb);
    cudaGetSymbolAddress((void**)&p_genxb, g_genxb);
    cudaGetSymbolAddress((void**)&p_mencbias, g_mencbias);
    cudaGetSymbolAddress((void**)&p_decbias, g_decbias);
    cudaGetSymbolAddress((void**)&p_mencxb, g_mencxb);
    cudaGetSymbolAddress((void**)&p_message, g_message);
    cudaGetSymbolAddress((void**)&p_decx, g_decx);
    cudaGetSymbolAddress((void**)&p_decxb, g_decxb);
    cudaGetSymbolAddress((void**)&p_dech, g_dech);

    const int SMEM_GEMM = 4 * TILE_U32 * (int)sizeof(uint32_t);  // 64 KB
    cudaFuncSetAttribute(k_gemm_tf32, cudaFuncAttributeMaxDynamicSharedMemorySize, SMEM_GEMM);

    const int BH_BLKS = (BSZ * HN) / 256;

    // ---- prep ----
    k_escore<<<VN, 256>>>(embedding, attn_w);
    k_c0s<<<1, 256>>>(set_h0, attn_w);
    k_vecproj<<<16, 256>>>(set_h0, set_Whh, set_bih, set_bhh, p_sethb, HN);
    k_vecproj<<<16, 256>>>(gen_x0, gen_Wih, gen_bih, gen_bhh, p_genxb, MVN);
    k_vecproj<<<16, 256>>>(set_h0, set_Whh, menc_bih, menc_bhh, p_mencbias, 0);
    k_vecproj<<<16, 256>>>(set_h0, set_Whh, dec_bih, dec_bhh, p_decbias, 0);
    k_minit<<<2, 256>>>();

    // ---- attention + encoder step ----
    k_attn<<<BSZ, 256>>>(input_var, input_mask, embedding, attn_b);
    k_gemm_tf32<<<dim3(H4 / 128, BSZ / 128), 256, SMEM_GEMM>>>(p_r, set_Wih, p_sethb, nullptr,
                                                               p_gates, BSZ, H4, HN);
    k_lstm_pw<<<BH_BLKS, 256>>>(set_c0, 0, -1);

    // ---- gen loop ----
    for (int t = 0; t < LN; t++) {
        k_gemm_tf32<<<dim3(H4 / 128, BSZ / 128), 256, SMEM_GEMM>>>(p_h, gen_Whh, p_genxb, nullptr,
                                                                   p_gates, BSZ, H4, HN);
        k_lstm_pw<<<BH_BLKS, 256>>>(p_c, HN, -1);
        k_genout<<<BSZ, 256>>>(gen_outW, gen_outb, t);
    }

    // ---- message encoder ----
    k_bcast_hc<<<BH_BLKS, 256>>>(menc_h0, menc_c0);
    k_gemm_tf32<<<dim3(H4 / 128, (LN * BSZ) / 128), 256, SMEM_GEMM>>>(
        p_message, menc_Wih, p_mencbias, nullptr, p_mencxb, LN * BSZ, H4, MVN);
    for (int t = 0; t < LN; t++) {
        k_gemm_tf32<<<dim3(H4 / 128, BSZ / 128), 256, SMEM_GEMM>>>(
            p_h, menc_Whh, nullptr, p_mencxb + (size_t)t * BSZ * H4, p_gates, BSZ, H4, HN);
        k_lstm_pw_masked<<<BH_BLKS, 256>>>(t);
    }

    // ---- decoder ----
    k_decx<<<(TN * BSZ * HN) / 256, 256>>>(target_var, embedding);
    k_gemm_tf32<<<dim3(H4 / 128, (TN * BSZ) / 128), 256, SMEM_GEMM>>>(
        p_decx, dec_Wih, p_decbias, nullptr, p_decxb, TN * BSZ, H4, HN);
    for (int t = 0; t < TN; t++) {
        k_gemm_tf32<<<dim3(H4 / 128, BSZ / 128), 256, SMEM_GEMM>>>(
            p_h, dec_Whh, nullptr, p_decxb + (size_t)t * BSZ * H4, p_gates, BSZ, H4, HN);
        k_lstm_pw<<<BH_BLKS, 256>>>(p_c, HN, t);
    }
    k_gemm_tf32<<<dim3(VN / 128, (TN * BSZ) / 128), 256, SMEM_GEMM>>>(
        p_dech, dec_outW, dec_outb, nullptr, (float*)d_out, TN * BSZ, VN, HN);
}